// round 10
// baseline (speedup 1.0000x reference)
#include <cuda_runtime.h>
#include <stdint.h>
#include <float.h>

// Shapes: data [64,1024,256] f32, locs [64,256,2] f32, out [64,1024,2500] f32
#define B_  64
#define T_  1024
#define N_  256
#define G_  50
#define GG  2500
#define TPB 256
#define T_PER_BLOCK 32
#define R_  8                   // t-rows per barrier window (gather)
#define CELLS_PER_BLOCK 128     // nearest: 2 threads per cell
#define NB_X ((GG + CELLS_PER_BLOCK - 1) / CELLS_PER_BLOCK)   // 20

__device__ uint8_t g_nearest[B_ * GG];

// ---------------------------------------------------------------------------
// Kernel A: argmin_j sqrt((sx-gx)^2+(sy-gy)^2), bit-exact vs jnp reference.
// 2 threads per cell, each scans 128 sensors => 2x warps, half-length chains
// (latency-bound fix: ~17 warps/SMSP saturates issue).
//  Pass 1: branchless min of e_j = c_j - 2sx*gx - 2sy*gy, 4 accumulators.
//          |e - shifted d2| <= ~3e-3; fp32 sqrt-tie class width <= ~1.5e-3
//          => thresh = emin + 0.02 covers every possible winner.
//  Pass 2: for rare e<=thresh, EXACT reference d2 (rn mul/add, no FMA
//          contraction) + __fsqrt_rn; key = (bits(sq)<<32)|j, min over the
//          pair via shfl => lexicographic (sq, j) min = first-index-wins,
//          identical to jnp.argmin(sqrt(...)).  (validated rel_err=0 R4-R9)
// ---------------------------------------------------------------------------
__global__ __launch_bounds__(TPB)
void nearest_kernel(const float* __restrict__ locs) {
    __shared__ float4 ssen[N_];   // {sx, sy, c, 0}
    const int b    = blockIdx.y;
    const int tid  = threadIdx.x;
    const int half = tid & 1;             // which 128 sensors this thread scans
    const int cell = blockIdx.x * CELLS_PER_BLOCK + (tid >> 1);
    const bool valid = (cell < GG);

    {
        float2 l = reinterpret_cast<const float2*>(locs)[b * N_ + tid];
        float sx = __fadd_rn(__fmul_rn(l.x, 25.0f), 25.0f);   // exact ref transform
        float sy = __fadd_rn(__fmul_rn(l.y, 25.0f), 25.0f);
        ssen[tid] = make_float4(sx, sy, sx * sx + sy * sy, 0.0f);
    }
    __syncthreads();

    const int c  = valid ? cell : 0;
    const float gx = (float)(c / G_);
    const float gy = (float)(c % G_);
    const float ax = -2.0f * gx, ay = -2.0f * gy;   // exact small ints
    const int  j0 = half * 128;

    // Pass 1: branchless e-min over this thread's 128 sensors (4 accumulators)
    float m0 = FLT_MAX, m1 = FLT_MAX, m2 = FLT_MAX, m3 = FLT_MAX;
    #pragma unroll 8
    for (int i = 0; i < 128; i += 4) {
        float4 s0 = ssen[j0 + i + 0];
        float4 s1 = ssen[j0 + i + 1];
        float4 s2 = ssen[j0 + i + 2];
        float4 s3 = ssen[j0 + i + 3];
        m0 = fminf(m0, __fmaf_rn(s0.y, ay, __fmaf_rn(s0.x, ax, s0.z)));
        m1 = fminf(m1, __fmaf_rn(s1.y, ay, __fmaf_rn(s1.x, ax, s1.z)));
        m2 = fminf(m2, __fmaf_rn(s2.y, ay, __fmaf_rn(s2.x, ax, s2.z)));
        m3 = fminf(m3, __fmaf_rn(s3.y, ay, __fmaf_rn(s3.x, ax, s3.z)));
    }
    float emin = fminf(fminf(m0, m1), fminf(m2, m3));
    // pair-combine (lanes 2k,2k+1 share a cell)
    emin = fminf(emin, __shfl_xor_sync(0xFFFFFFFFu, emin, 1));
    const float thresh = emin + 0.02f;

    // Pass 2: exact evaluation for rare candidates within this thread's half
    unsigned long long key = ~0ull;
    #pragma unroll 8
    for (int i = 0; i < 128; ++i) {
        const int j = j0 + i;
        float4 sv = ssen[j];
        float e = __fmaf_rn(sv.y, ay, __fmaf_rn(sv.x, ax, sv.z));
        if (e <= thresh) {                            // ~0.5 hits per thread
            float dx = __fsub_rn(sv.x, gx);
            float dy = __fsub_rn(sv.y, gy);
            float d2 = __fadd_rn(__fmul_rn(dx, dx), __fmul_rn(dy, dy));
            float sq = __fsqrt_rn(d2);                // exact reference value
            unsigned long long k =
                ((unsigned long long)__float_as_uint(sq) << 32) | (unsigned)j;
            key = (k < key) ? k : key;
        }
    }
    {   // pair-combine: lexicographic (sq, j) min => first-index-wins
        unsigned long long other = __shfl_xor_sync(0xFFFFFFFFu, key, 1);
        key = (other < key) ? other : key;
    }
    if (valid && half == 0)
        g_nearest[b * GG + cell] = (uint8_t)(key & 0xFFu);
}

// ---------------------------------------------------------------------------
// Kernel B (R6, best measured 119.97us): out[b,t,g] = data[b,t,nearest[b,g]]
// ---------------------------------------------------------------------------
__global__ __launch_bounds__(TPB)
void gather_kernel(const float* __restrict__ data, float* __restrict__ out) {
    __shared__ float4  rowsA[N_];
    __shared__ float4  rowsB[N_];
    __shared__ uint8_t sidx[GG];

    const int b   = blockIdx.y;
    const int tid = threadIdx.x;

    {
        const uint32_t* src = reinterpret_cast<const uint32_t*>(g_nearest + (size_t)b * GG);
        uint32_t* dst = reinterpret_cast<uint32_t*>(sidx);
        #pragma unroll
        for (int k = tid; k < GG / 4; k += TPB) dst[k] = src[k];
    }
    __syncthreads();

    int idx[3][4];
    #pragma unroll
    for (int gi = 0; gi < 3; ++gi) {
        int k = tid + gi * TPB;
        if (k < GG / 4) {
            idx[gi][0] = sidx[4 * k + 0];
            idx[gi][1] = sidx[4 * k + 1];
            idx[gi][2] = sidx[4 * k + 2];
            idx[gi][3] = sidx[4 * k + 3];
        }
    }

    const int t0 = blockIdx.x * T_PER_BLOCK;
    const float* dbase = data + ((size_t)b * T_ + t0) * (size_t)N_;
    float*       obase = out  + ((size_t)b * T_ + t0) * (size_t)GG;

    #pragma unroll 1
    for (int w = 0; w < T_PER_BLOCK / R_; ++w) {
        __syncthreads();
        {
            const float* d0 = dbase + (size_t)(w * R_) * N_ + tid;
            float4 va, vb;
            va.x = __ldcs(d0 + 0 * N_);
            va.y = __ldcs(d0 + 1 * N_);
            va.z = __ldcs(d0 + 2 * N_);
            va.w = __ldcs(d0 + 3 * N_);
            vb.x = __ldcs(d0 + 4 * N_);
            vb.y = __ldcs(d0 + 5 * N_);
            vb.z = __ldcs(d0 + 6 * N_);
            vb.w = __ldcs(d0 + 7 * N_);
            rowsA[tid] = va;
            rowsB[tid] = vb;
        }
        __syncthreads();

        float* o = obase + (size_t)(w * R_) * GG;
        #pragma unroll
        for (int gi = 0; gi < 3; ++gi) {
            int k = tid + gi * TPB;
            if (k < GG / 4) {
                float4 a0 = rowsA[idx[gi][0]];
                float4 a1 = rowsA[idx[gi][1]];
                float4 a2 = rowsA[idx[gi][2]];
                float4 a3 = rowsA[idx[gi][3]];
                __stcs(reinterpret_cast<float4*>(o + 0 * GG) + k,
                       make_float4(a0.x, a1.x, a2.x, a3.x));
                __stcs(reinterpret_cast<float4*>(o + 1 * GG) + k,
                       make_float4(a0.y, a1.y, a2.y, a3.y));
                __stcs(reinterpret_cast<float4*>(o + 2 * GG) + k,
                       make_float4(a0.z, a1.z, a2.z, a3.z));
                __stcs(reinterpret_cast<float4*>(o + 3 * GG) + k,
                       make_float4(a0.w, a1.w, a2.w, a3.w));
                float4 b0 = rowsB[idx[gi][0]];
                float4 b1 = rowsB[idx[gi][1]];
                float4 b2 = rowsB[idx[gi][2]];
                float4 b3 = rowsB[idx[gi][3]];
                __stcs(reinterpret_cast<float4*>(o + 4 * GG) + k,
                       make_float4(b0.x, b1.x, b2.x, b3.x));
                __stcs(reinterpret_cast<float4*>(o + 5 * GG) + k,
                       make_float4(b0.y, b1.y, b2.y, b3.y));
                __stcs(reinterpret_cast<float4*>(o + 6 * GG) + k,
                       make_float4(b0.z, b1.z, b2.z, b3.z));
                __stcs(reinterpret_cast<float4*>(o + 7 * GG) + k,
                       make_float4(b0.w, b1.w, b2.w, b3.w));
            }
        }
    }
}

// ---------------------------------------------------------------------------
extern "C" void kernel_launch(void* const* d_in, const int* in_sizes, int n_in,
                              void* d_out, int out_size) {
    const float* data = (const float*)d_in[0];
    const float* locs = (const float*)d_in[1];
    if (n_in >= 2 && in_sizes[0] < in_sizes[1]) {
        data = (const float*)d_in[1];
        locs = (const float*)d_in[0];
    }
    float* out = (float*)d_out;

    dim3 gridA(NB_X, B_);                 // 20 x 64 = 1280 blocks, 2 thr/cell
    nearest_kernel<<<gridA, TPB>>>(locs);

    dim3 gridB(T_ / T_PER_BLOCK, B_);     // 32 x 64 blocks
    gather_kernel<<<gridB, TPB>>>(data, out);
}